// round 2
// baseline (speedup 1.0000x reference)
#include <cuda_runtime.h>
#include <cstdint>

// Problem constants
#define EMB 128
#define INT_EMB 64
#define NRAD 6
#define NSPH 7
#define NSR (NRAD*NSPH)   // 42
#define BASIS 8
#define E_EDGES 262144
#define T_TRIP 2097152

typedef unsigned long long ull;

// ---------------- scratch (device globals; no allocation allowed) -------------
__device__ float g_Wr[NRAD*EMB];                 // fused rbf weight 6x128
__device__ float g_xji[(size_t)E_EDGES*EMB];     // 128 MiB
__device__ float g_tmp[(size_t)E_EDGES*EMB];     // 128 MiB
__device__ float g_upd[(size_t)E_EDGES*EMB];     // 128 MiB
__device__ float g_xkj2[(size_t)E_EDGES*INT_EMB];// 64 MiB
__device__ float g_agg[(size_t)E_EDGES*INT_EMB]; // 64 MiB

// ---------------- packed f32x2 helpers ---------------------------------------
__device__ __forceinline__ ull pack2(float x, float y) {
    ull r; asm("mov.b64 %0,{%1,%2};" : "=l"(r) : "f"(x), "f"(y)); return r;
}
__device__ __forceinline__ void unpack2(ull v, float& x, float& y) {
    asm("mov.b64 {%0,%1},%2;" : "=f"(x), "=f"(y) : "l"(v));
}
__device__ __forceinline__ ull ffma2(ull a, ull b, ull c) {
    ull d; asm("fma.rn.f32x2 %0,%1,%2,%3;" : "=l"(d) : "l"(a), "l"(b), "l"(c)); return d;
}
__device__ __forceinline__ float silu_f(float x) {
    return x * (1.0f / (1.0f + __expf(-x)));
}

// ---------------- K0: fuse W_rbf1 @ W_rbf2 -> g_Wr [6][128] -------------------
__global__ void fuse_wr_kernel(const float* __restrict__ W1 /*6x8*/,
                               const float* __restrict__ W2 /*8x128*/) {
    int i = blockIdx.x * blockDim.x + threadIdx.x;
    if (i < NRAD * EMB) {
        int r = i / EMB, n = i % EMB;
        float s = 0.f;
#pragma unroll
        for (int b = 0; b < BASIS; b++) s += W1[r*BASIS + b] * W2[b*EMB + n];
        g_Wr[i] = s;
    }
}

// ---------------- zero g_agg --------------------------------------------------
__global__ void zero_agg_kernel() {
    size_t i = (size_t)blockIdx.x * blockDim.x + threadIdx.x;
    float4 z = {0.f, 0.f, 0.f, 0.f};
    ((float4*)g_agg)[i] = z;   // grid sized exactly
}

// ---------------- generic fused GEMM: out = [res +] act(A@W [+ b]) [* rbf_e] --
// A: [M x K] row-major, W: [K x N] row-major, out: [M x N]
// BM=128, BK=8, 256 threads. Microtile TM x 8 cols (as 4 f32x2 pairs).
template<int N, int K, bool MUL_RBF, bool ADD_RES>
__global__ __launch_bounds__(256, 2)
void gemm_silu_kernel(const float* __restrict__ A,
                      const float* __restrict__ W,
                      const float* __restrict__ bias,   // may be null
                      const float* __restrict__ res,    // used if ADD_RES
                      const float* __restrict__ rbf,    // [E,6] if MUL_RBF
                      float* __restrict__ out) {
    constexpr int BM = 128, BK = 8;
    constexpr int TX = N / 8;       // 16 (N=128) or 8 (N=64)
    constexpr int TY = 256 / TX;    // 16 or 32
    constexpr int TM = BM / TY;     // 8 or 4

    __shared__ __align__(16) float As[BK][BM];
    __shared__ __align__(16) float Bs[BK][N];
    __shared__ float Wr_s[MUL_RBF ? NRAD*EMB : 1];

    const int tid = threadIdx.x;
    const int tx = tid % TX, ty = tid / TX;
    const int m0 = blockIdx.x * BM;

    if (MUL_RBF) {
        for (int i = tid; i < NRAD*EMB; i += 256) Wr_s[i] = g_Wr[i];
    }

    ull acc[TM][4];
#pragma unroll
    for (int i = 0; i < TM; i++)
#pragma unroll
        for (int j = 0; j < 4; j++) acc[i][j] = 0ull;

    for (int kt = 0; kt < K / BK; kt++) {
        // A tile: 128x8 = 1024 floats, one float4 per thread, stored transposed
        {
            int r = tid >> 1;
            int kq = (tid & 1) * 4;
            const float4 a4 = *(const float4*)&A[(size_t)(m0 + r) * K + kt*BK + kq];
            As[kq+0][r] = a4.x; As[kq+1][r] = a4.y;
            As[kq+2][r] = a4.z; As[kq+3][r] = a4.w;
        }
        // B tile: 8xN floats
        if (N == 128) {
            int k = tid >> 5, c = (tid & 31) * 4;
            *(float4*)&Bs[k][c] = *(const float4*)&W[(size_t)(kt*BK + k) * N + c];
        } else { // N == 64
            if (tid < 128) {
                int k = tid >> 4, c = (tid & 15) * 4;
                *(float4*)&Bs[k][c] = *(const float4*)&W[(size_t)(kt*BK + k) * N + c];
            }
        }
        __syncthreads();

#pragma unroll
        for (int k = 0; k < BK; k++) {
            ull b[4];
            const ull* brow = (const ull*)&Bs[k][0];
#pragma unroll
            for (int j = 0; j < 4; j++) b[j] = brow[tx + TX*j];
#pragma unroll
            for (int i = 0; i < TM; i++) {
                float a = As[k][ty*TM + i];
                ull aa = pack2(a, a);
#pragma unroll
                for (int j = 0; j < 4; j++) acc[i][j] = ffma2(aa, b[j], acc[i][j]);
            }
        }
        __syncthreads();
    }

    // epilogue
    float2 bv[4];
#pragma unroll
    for (int j = 0; j < 4; j++) {
        if (bias) bv[j] = *(const float2*)&bias[2*(tx + TX*j)];
        else      bv[j] = make_float2(0.f, 0.f);
    }

#pragma unroll
    for (int i = 0; i < TM; i++) {
        const int row = m0 + ty*TM + i;
        float r6[NRAD];
        if (MUL_RBF) {
#pragma unroll
            for (int l = 0; l < NRAD; l++) r6[l] = rbf[(size_t)row*NRAD + l];
        }
#pragma unroll
        for (int j = 0; j < 4; j++) {
            const int c0 = 2*(tx + TX*j);
            float x, y; unpack2(acc[i][j], x, y);
            x += bv[j].x; y += bv[j].y;
            x = silu_f(x); y = silu_f(y);
            if (MUL_RBF) {
                float ex = 0.f, ey = 0.f;
#pragma unroll
                for (int l = 0; l < NRAD; l++) {
                    ex += r6[l] * Wr_s[l*EMB + c0];
                    ey += r6[l] * Wr_s[l*EMB + c0 + 1];
                }
                x *= ex; y *= ey;
            }
            if (ADD_RES) {
                const float2 rr = *(const float2*)&res[(size_t)row*N + c0];
                x += rr.x; y += rr.y;
            }
            float2 o; o.x = x; o.y = y;
            *(float2*)&out[(size_t)row*N + c0] = o;
        }
    }
}

// ---------------- triplet kernel ---------------------------------------------
// For each triplet t: tmp8 = sbf[t] @ W_sbf1 (42->8); out64 = tmp8 @ W_sbf2 (8->64)
// msg = x_kj2[src[t]] * out64; atomic segment-sum into g_agg[dst[t]].
// 256 threads = 16 half-warps; each half-warp handles one triplet (4 ch/lane).
__global__ __launch_bounds__(256)
void triplet_kernel(const float* __restrict__ sbf,
                    const int* __restrict__ src_idx,
                    const int* __restrict__ dst_idx,
                    const float* __restrict__ W1 /*42x8*/,
                    const float* __restrict__ W2 /*8x64*/) {
    __shared__ float sbf_s[16*NSR];          // 672
    __shared__ float W1s[NSR*BASIS];         // 336
    __shared__ __align__(16) float W2s[BASIS*INT_EMB]; // 512
    __shared__ float t8[16][BASIS];

    const int tid = threadIdx.x;
    for (int i = tid; i < NSR*BASIS; i += 256) W1s[i] = W1[i];
    for (int i = tid; i < BASIS*INT_EMB; i += 256) W2s[i] = W2[i];

    const int ngroups = T_TRIP / 16;
    const int half = tid >> 4;   // triplet within group
    const int l16  = tid & 15;   // 4-channel slot

    for (int g = blockIdx.x; g < ngroups; g += gridDim.x) {
        const size_t base = (size_t)g * (16*NSR);
        for (int i = tid; i < 16*NSR; i += 256) sbf_s[i] = sbf[base + i];
        __syncthreads();

        if (tid < 128) {
            int tt = tid >> 3, j = tid & 7;
            float s = 0.f;
#pragma unroll
            for (int r = 0; r < NSR; r++) s += sbf_s[tt*NSR + r] * W1s[r*BASIS + j];
            t8[tt][j] = s;
        }
        __syncthreads();

        const int t = g*16 + half;
        const int src = src_idx[t];
        const int dst = dst_idx[t];

        float4 a = {0.f, 0.f, 0.f, 0.f};
#pragma unroll
        for (int j = 0; j < BASIS; j++) {
            const float tv = t8[half][j];
            const float4 w = *(const float4*)&W2s[j*INT_EMB + l16*4];
            a.x += tv*w.x; a.y += tv*w.y; a.z += tv*w.z; a.w += tv*w.w;
        }
        const float4 xk = *(const float4*)(g_xkj2 + (size_t)src*INT_EMB + l16*4);
        a.x *= xk.x; a.y *= xk.y; a.z *= xk.z; a.w *= xk.w;

        atomicAdd((float4*)(g_agg + (size_t)dst*INT_EMB + l16*4), a);
        __syncthreads();
    }
}

// ---------------- host launcher ----------------------------------------------
extern "C" void kernel_launch(void* const* d_in, const int* in_sizes, int n_in,
                              void* d_out, int out_size) {
    const float* m       = (const float*)d_in[0];
    const float* rbf     = (const float*)d_in[1];
    const float* sbf     = (const float*)d_in[2];
    const int*   src_idx = (const int*)d_in[3];
    const int*   dst_idx = (const int*)d_in[4];
    const float* W_rbf1  = (const float*)d_in[5];
    const float* W_rbf2  = (const float*)d_in[6];
    const float* W_sbf1  = (const float*)d_in[7];
    const float* W_sbf2  = (const float*)d_in[8];
    const float* W_ji    = (const float*)d_in[9];
    const float* b_ji    = (const float*)d_in[10];
    const float* W_kj    = (const float*)d_in[11];
    const float* b_kj    = (const float*)d_in[12];
    const float* W_down  = (const float*)d_in[13];
    const float* W_up    = (const float*)d_in[14];
    const float* Wb1     = (const float*)d_in[15];
    const float* bb1     = (const float*)d_in[16];
    const float* Wb2     = (const float*)d_in[17];
    const float* bb2     = (const float*)d_in[18];
    const float* W_final = (const float*)d_in[19];
    const float* b_final = (const float*)d_in[20];
    const float* Wa1     = (const float*)d_in[21];
    const float* ba1     = (const float*)d_in[22];
    const float* Wa2     = (const float*)d_in[23];
    const float* ba2     = (const float*)d_in[24];
    float* out = (float*)d_out;

    // scratch pointers
    float *p_xji, *p_tmp, *p_upd, *p_xkj2, *p_agg;
    cudaGetSymbolAddress((void**)&p_xji,  g_xji);
    cudaGetSymbolAddress((void**)&p_tmp,  g_tmp);
    cudaGetSymbolAddress((void**)&p_upd,  g_upd);
    cudaGetSymbolAddress((void**)&p_xkj2, g_xkj2);
    cudaGetSymbolAddress((void**)&p_agg,  g_agg);

    const int GB = E_EDGES / 128;   // 2048 gemm blocks

    // K0: fused rbf weight
    fuse_wr_kernel<<<3, 256>>>(W_rbf1, W_rbf2);

    // zero aggregation buffer (E*64 floats / 4 per thread / 256 per block)
    zero_agg_kernel<<<(E_EDGES*INT_EMB/4)/256, 256>>>();

    // x_ji = silu(m @ W_ji + b_ji)
    gemm_silu_kernel<128,128,false,false><<<GB,256>>>(m, W_ji, b_ji, nullptr, nullptr, p_xji);
    // xkjm = silu(m @ W_kj + b_kj) * rbf_e
    gemm_silu_kernel<128,128,true ,false><<<GB,256>>>(m, W_kj, b_kj, nullptr, rbf, p_tmp);
    // x_kj2 = silu(xkjm @ W_down)
    gemm_silu_kernel<64 ,128,false,false><<<GB,256>>>(p_tmp, W_down, nullptr, nullptr, nullptr, p_xkj2);

    // triplet message + segment sum
    triplet_kernel<<<4096, 256>>>(sbf, src_idx, dst_idx, W_sbf1, W_sbf2);

    // upd = x_ji + silu(agg @ W_up)
    gemm_silu_kernel<128,64 ,false,true ><<<GB,256>>>(p_agg, W_up, nullptr, p_xji, nullptr, p_upd);
    // residual-before (N_BEFORE=1)
    gemm_silu_kernel<128,128,false,false><<<GB,256>>>(p_upd, Wb1, bb1, nullptr, nullptr, p_tmp);
    gemm_silu_kernel<128,128,false,true ><<<GB,256>>>(p_tmp, Wb2, bb2, p_upd, nullptr, p_upd);
    // final: out = m + silu(upd @ W_final + b_final)
    gemm_silu_kernel<128,128,false,true ><<<GB,256>>>(p_upd, W_final, b_final, m, nullptr, out);
    // residual-after (N_AFTER=2)
    gemm_silu_kernel<128,128,false,false><<<GB,256>>>(out, Wa1,           ba1,       nullptr, nullptr, p_tmp);
    gemm_silu_kernel<128,128,false,true ><<<GB,256>>>(p_tmp, Wa2,         ba2,       out,     nullptr, out);
    gemm_silu_kernel<128,128,false,false><<<GB,256>>>(out, Wa1 + 128*128, ba1 + 128, nullptr, nullptr, p_tmp);
    gemm_silu_kernel<128,128,false,true ><<<GB,256>>>(p_tmp, Wa2 + 128*128, ba2 + 128, out,   nullptr, out);
}